// round 11
// baseline (speedup 1.0000x reference)
#include <cuda_runtime.h>
#include <cuda_bf16.h>
#include <math.h>
#include <stdint.h>
#include <mma.h>

using namespace nvcuda;

// ---------------------------------------------------------------------------
// RGCN, GEMM-first + CSR gather. Pipelined wmma tf32 GEMM (128x64 CTA tile,
// KC=32 double-buffered, 3 CTAs/SM target).
//   z_r = x @ W1_r ; h[d] = relu(sum_e coef_e * z[rel_e][src_e] + b1sum)
//   y_r = h @ W2_r ; out[d] =   sum_e coef_e * y[rel_e][src_e] + b2sum
// ---------------------------------------------------------------------------

#define NREL 4
#define INF  128
#define HF   128
#define OUTF 64
#define MAXN 100000
#define MAXE 400000
#define MAXT ((MAXN + 127) / 128)
#define MAXP (MAXT * 128)
#define SCAN_B 1024

__device__ float g_z[(size_t)NREL * MAXP * HF];
__device__ float g_y[(size_t)NREL * MAXP * OUTF];
__device__ float g_h[(size_t)MAXN * HF];
__device__ float g_deg_src[NREL * MAXN];
__device__ float g_deg_dst[NREL * MAXN];
__device__ int   g_cnt[MAXN + 1];
__device__ int   g_off[MAXN + 1];
__device__ int   g_cursor[MAXN];
__device__ int   g_bsum[128];
__device__ int   g_boff[128];
__device__ int2  g_edge[NREL * MAXE];   // .x = src | rel<<20, .y = coef bits
__device__ int   g_idx64;

__device__ __forceinline__ int load_idx(const void* p, size_t i, int is64) {
    return is64 ? (int)((const long long*)p)[i] : ((const int*)p)[i];
}

// ---------------------------------------------------------------------------
__global__ void init_kernel(const unsigned int* __restrict__ words, int n_words,
                            float* __restrict__ ds, float* __restrict__ dd, int nrs,
                            int* __restrict__ cnt, int* __restrict__ cur, int n) {
    if (blockIdx.x == 0) {
        int limit = n_words < 4096 ? n_words : 4096;
        int bad = 0;
        for (int i = 1 + 2 * (int)threadIdx.x; i < limit; i += 2 * (int)blockDim.x)
            bad |= (words[i] != 0u);
        bad = __syncthreads_or(bad);
        if (threadIdx.x == 0) g_idx64 = bad ? 0 : 1;
    }
    int i = blockIdx.x * blockDim.x + threadIdx.x;
    int st = gridDim.x * blockDim.x;
    for (int k = i; k < nrs; k += st) { ds[k] = 0.0f; dd[k] = 0.0f; }
    for (int k = i; k < n; k += st)   { cnt[k] = 0; cur[k] = 0; }
}

__global__ void degree_kernel(const void* __restrict__ src, const void* __restrict__ dst,
                              float* __restrict__ ds, float* __restrict__ dd,
                              int* __restrict__ cnt, int E, int M) {
    int i = blockIdx.x * blockDim.x + threadIdx.x;
    if (i >= NREL * E) return;
    const int is64 = g_idx64;
    int r = i / E;
    int s = load_idx(src, i, is64);
    int d = load_idx(dst, i, is64);
    atomicAdd(&ds[r * M + s], 1.0f);
    atomicAdd(&dd[r * M + d], 1.0f);
    atomicAdd(&cnt[d], 1);
}

// ---------------------------------------------------------------------------
__device__ __forceinline__ int block_incl_scan(int v, int* wsum) {
    const int lane = threadIdx.x & 31, wid = threadIdx.x >> 5;
    int s = v;
#pragma unroll
    for (int o = 1; o < 32; o <<= 1) {
        int t = __shfl_up_sync(~0u, s, o);
        if (lane >= o) s += t;
    }
    if (lane == 31) wsum[wid] = s;
    __syncthreads();
    if (wid == 0) {
        int ws = (lane < (SCAN_B / 32)) ? wsum[lane] : 0;
#pragma unroll
        for (int o = 1; o < 32; o <<= 1) {
            int t = __shfl_up_sync(~0u, ws, o);
            if (lane >= o) ws += t;
        }
        wsum[lane] = ws;
    }
    __syncthreads();
    return s + (wid > 0 ? wsum[wid - 1] : 0);
}

__global__ void scanA_kernel(const int* __restrict__ cnt, int* __restrict__ bsum, int n) {
    __shared__ int wsum[32];
    int i = blockIdx.x * SCAN_B + threadIdx.x;
    int v = (i < n) ? cnt[i] : 0;
    int s = block_incl_scan(v, wsum);
    if (threadIdx.x == SCAN_B - 1) bsum[blockIdx.x] = s;
}

__global__ void scanB_kernel(const int* __restrict__ bsum, int* __restrict__ boff,
                             int* __restrict__ off, int nb, int n) {
    const int lane = threadIdx.x;
    int carry = 0;
    for (int base = 0; base < nb; base += 32) {
        int i = base + lane;
        int v = (i < nb) ? bsum[i] : 0;
        int s = v;
#pragma unroll
        for (int o = 1; o < 32; o <<= 1) {
            int t = __shfl_up_sync(~0u, s, o);
            if (lane >= o) s += t;
        }
        if (i < nb) boff[i] = carry + s - v;
        carry += __shfl_sync(~0u, s, 31);
    }
    if (lane == 0) off[n] = carry;
}

__global__ void scanC_kernel(const int* __restrict__ cnt, const int* __restrict__ boff,
                             int* __restrict__ off, int n) {
    __shared__ int wsum[32];
    int i = blockIdx.x * SCAN_B + threadIdx.x;
    int v = (i < n) ? cnt[i] : 0;
    int s = block_incl_scan(v, wsum);
    if (i < n) off[i] = boff[blockIdx.x] + s - v;
}

// ---------------------------------------------------------------------------
__global__ void fill_kernel(const void* __restrict__ src, const void* __restrict__ dst,
                            const float* __restrict__ ds, const float* __restrict__ dd,
                            const int* __restrict__ off, int* __restrict__ cur,
                            int2* __restrict__ edge, int E, int M) {
    int i = blockIdx.x * blockDim.x + threadIdx.x;
    if (i >= NREL * E) return;
    const int is64 = g_idx64;
    int r = i / E;
    int s = load_idx(src, i, is64);
    int d = load_idx(dst, i, is64);
    int pos = off[d] + atomicAdd(&cur[d], 1);
    float coef = rsqrtf(fmaxf(ds[r * M + s], 1.0f)) *
                 rsqrtf(fmaxf(dd[r * M + d], 1.0f));
    edge[pos] = make_int2(s | (r << 20), __float_as_int(coef));
}

// ---------------------------------------------------------------------------
// Pipelined wmma tf32 GEMM. CTA tile 128(M) x 64(N); K=128 in 4 chunks of 32,
// double-buffered SMEM; A-chunk prefetched to registers across the MMA phase.
// C[r][m][col0:col0+64] = A[m][:] @ B[r][:][col0:col0+64]; C padded to Mp rows.
// ---------------------------------------------------------------------------
#define KC 32
#define A_STRIDE (KC + 4)     // 36
#define B_STRIDE (64 + 4)     // 68
#define A_BUF (128 * A_STRIDE)
#define B_BUF (KC * B_STRIDE)

template <int NF>
__global__ __launch_bounds__(256, 3)
void gemm_kernel(const float* __restrict__ A, const float* __restrict__ B,
                 float* __restrict__ C, int M, int Mp) {
    extern __shared__ float sm[];
    float* As = sm;                    // [2][128][36]
    float* Bs = sm + 2 * A_BUF;        // [2][32][68]

    const int r    = blockIdx.y;
    const int col0 = blockIdx.z * 64;
    const int row0 = blockIdx.x * 128;
    const int tid  = threadIdx.x;
    const int wid  = tid >> 5;
    const float* Bb = B + (size_t)r * 128 * NF + col0;

    // thread's fixed slots for staging
    const int arr = tid >> 1;                 // A row (0..127), 2 threads/row
    const int acc_ = (tid & 1) * 16;          // A col base: 16 floats = 4 float4
    const int brr = tid >> 4;                 // B row (0..15), +16 for second half
    const int bcc = (tid & 15) * 4;           // B col

    // prologue: stage chunk 0 into buffer 0
    {
        const int gr = row0 + arr;
        const float* Arow = A + (size_t)gr * 128 + acc_;
#pragma unroll
        for (int j = 0; j < 4; j++) {
            float4 v = (gr < M) ? *(const float4*)(Arow + j * 4)
                                : make_float4(0.f, 0.f, 0.f, 0.f);
            float* p = As + arr * A_STRIDE + acc_ + j * 4;
            p[0] = wmma::__float_to_tf32(v.x);
            p[1] = wmma::__float_to_tf32(v.y);
            p[2] = wmma::__float_to_tf32(v.z);
            p[3] = wmma::__float_to_tf32(v.w);
        }
#pragma unroll
        for (int j = 0; j < 2; j++) {
            int rr = brr + j * 16;
            float4 v = *(const float4*)(Bb + (size_t)rr * NF + bcc);
            float* p = Bs + rr * B_STRIDE + bcc;
            p[0] = wmma::__float_to_tf32(v.x);
            p[1] = wmma::__float_to_tf32(v.y);
            p[2] = wmma::__float_to_tf32(v.z);
            p[3] = wmma::__float_to_tf32(v.w);
        }
    }
    __syncthreads();

    wmma::fragment<wmma::accumulator, 16, 16, 8, float> acc[4];
#pragma unroll
    for (int n = 0; n < 4; n++) wmma::fill_fragment(acc[n], 0.0f);

#pragma unroll
    for (int kc = 0; kc < 4; kc++) {
        const int cur = kc & 1;
        float4 pa[4], pb[2];
        if (kc < 3) {
            // prefetch next chunk to registers (LDG overlaps MMA below)
            const int k0 = (kc + 1) * KC;
            const int gr = row0 + arr;
            const float* Arow = A + (size_t)gr * 128 + k0 + acc_;
#pragma unroll
            for (int j = 0; j < 4; j++)
                pa[j] = (gr < M) ? *(const float4*)(Arow + j * 4)
                                 : make_float4(0.f, 0.f, 0.f, 0.f);
#pragma unroll
            for (int j = 0; j < 2; j++)
                pb[j] = *(const float4*)(Bb + (size_t)(k0 + brr + j * 16) * NF + bcc);
        }
        // MMA on current buffer
        const float* Ab = As + cur * A_BUF + (wid * 16) * A_STRIDE;
        const float* Bc = Bs + cur * B_BUF;
#pragma unroll
        for (int kf = 0; kf < 4; kf++) {
            wmma::fragment<wmma::matrix_a, 16, 16, 8, wmma::precision::tf32,
                           wmma::row_major> afrag;
            wmma::load_matrix_sync(afrag, Ab + kf * 8, A_STRIDE);
#pragma unroll
            for (int n = 0; n < 4; n++) {
                wmma::fragment<wmma::matrix_b, 16, 16, 8, wmma::precision::tf32,
                               wmma::row_major> bfrag;
                wmma::load_matrix_sync(bfrag, Bc + (kf * 8) * B_STRIDE + n * 16,
                                       B_STRIDE);
                wmma::mma_sync(acc[n], afrag, bfrag, acc[n]);
            }
        }
        if (kc < 3) {
            const int nxt = cur ^ 1;
            float* pA = As + nxt * A_BUF + arr * A_STRIDE + acc_;
#pragma unroll
            for (int j = 0; j < 4; j++) {
                pA[j * 4 + 0] = wmma::__float_to_tf32(pa[j].x);
                pA[j * 4 + 1] = wmma::__float_to_tf32(pa[j].y);
                pA[j * 4 + 2] = wmma::__float_to_tf32(pa[j].z);
                pA[j * 4 + 3] = wmma::__float_to_tf32(pa[j].w);
            }
#pragma unroll
            for (int j = 0; j < 2; j++) {
                float* pB = Bs + nxt * B_BUF + (brr + j * 16) * B_STRIDE + bcc;
                pB[0] = wmma::__float_to_tf32(pb[j].x);
                pB[1] = wmma::__float_to_tf32(pb[j].y);
                pB[2] = wmma::__float_to_tf32(pb[j].z);
                pB[3] = wmma::__float_to_tf32(pb[j].w);
            }
            __syncthreads();
        }
    }

    // epilogue: direct store into padded C (Mp rows; no guard needed)
    float* Crow = C + ((size_t)r * Mp + row0 + wid * 16) * NF + col0;
#pragma unroll
    for (int n = 0; n < 4; n++)
        wmma::store_matrix_sync(Crow + n * 16, acc[n], NF, wmma::mem_row_major);
}

// ---------------------------------------------------------------------------
// gather1: warp per dst, 128 feats; h = relu(agg + b1sum)
__global__ __launch_bounds__(256)
void gather1_kernel(const float* __restrict__ Z, const int* __restrict__ off,
                    const int2* __restrict__ edge,
                    const float* __restrict__ b1, float* __restrict__ h,
                    int M, int Mp) {
    const int d = blockIdx.x * 8 + (threadIdx.x >> 5);
    const int lane = threadIdx.x & 31;
    if (d >= M) return;
    const int e0 = off[d], e1 = off[d + 1];
    float4 acc = make_float4(0.f, 0.f, 0.f, 0.f);
#pragma unroll 8
    for (int e = e0; e < e1; e++) {
        const int2 ed = __ldg(&edge[e]);
        const int s = ed.x & 0xFFFFF, r = ed.x >> 20;
        const float c = __int_as_float(ed.y);
        const float4 v = *(const float4*)(Z + ((size_t)r * Mp + s) * 128 + lane * 4);
        acc.x += c * v.x; acc.y += c * v.y; acc.z += c * v.z; acc.w += c * v.w;
    }
    const int f = lane * 4;
    float4 o;
    o.x = fmaxf(acc.x + b1[f+0] + b1[128+f+0] + b1[256+f+0] + b1[384+f+0], 0.f);
    o.y = fmaxf(acc.y + b1[f+1] + b1[128+f+1] + b1[256+f+1] + b1[384+f+1], 0.f);
    o.z = fmaxf(acc.z + b1[f+2] + b1[128+f+2] + b1[256+f+2] + b1[384+f+2], 0.f);
    o.w = fmaxf(acc.w + b1[f+3] + b1[128+f+3] + b1[256+f+3] + b1[384+f+3], 0.f);
    *(float4*)(h + (size_t)d * 128 + f) = o;
}

// gather2: half-warp per dst, 64 feats; out = agg + b2sum
__global__ __launch_bounds__(256)
void gather2_kernel(const float* __restrict__ Y, const int* __restrict__ off,
                    const int2* __restrict__ edge,
                    const float* __restrict__ b2, float* __restrict__ out,
                    int M, int Mp) {
    const int warp = blockIdx.x * 8 + (threadIdx.x >> 5);
    const int lane = threadIdx.x & 31;
    const int d = warp * 2 + (lane >> 4);
    const int fl = lane & 15;
    if (d >= M) return;
    const int e0 = off[d], e1 = off[d + 1];
    float4 acc = make_float4(0.f, 0.f, 0.f, 0.f);
#pragma unroll 8
    for (int e = e0; e < e1; e++) {
        const int2 ed = __ldg(&edge[e]);
        const int s = ed.x & 0xFFFFF, r = ed.x >> 20;
        const float c = __int_as_float(ed.y);
        const float4 v = *(const float4*)(Y + ((size_t)r * Mp + s) * 64 + fl * 4);
        acc.x += c * v.x; acc.y += c * v.y; acc.z += c * v.z; acc.w += c * v.w;
    }
    const int f = fl * 4;
    float4 o;
    o.x = acc.x + b2[f+0] + b2[64+f+0] + b2[128+f+0] + b2[192+f+0];
    o.y = acc.y + b2[f+1] + b2[64+f+1] + b2[128+f+1] + b2[192+f+1];
    o.z = acc.z + b2[f+2] + b2[64+f+2] + b2[128+f+2] + b2[192+f+2];
    o.w = acc.w + b2[f+3] + b2[64+f+3] + b2[128+f+3] + b2[192+f+3];
    *(float4*)(out + (size_t)d * 64 + f) = o;
}

// ---------------------------------------------------------------------------
extern "C" void kernel_launch(void* const* d_in, const int* in_sizes, int n_in,
                              void* d_out, int out_size) {
    const float* x    = (const float*)d_in[0];
    const void*  srcI = d_in[1];
    const void*  dstI = d_in[2];
    const float* W1   = (const float*)d_in[3];
    const float* b1   = (const float*)d_in[4];
    const float* W2   = (const float*)d_in[5];
    const float* b2   = (const float*)d_in[6];
    float*       out  = (float*)d_out;

    const int M = in_sizes[0] / INF;
    const int E = in_sizes[1] / NREL;
    const int tiles = (M + 127) / 128;
    const int Mp = tiles * 128;
    const int NB = (M + SCAN_B - 1) / SCAN_B;

    float *z, *y, *h, *ds, *dd;
    int *cnt, *off, *cur, *bsum, *boff;
    int2 *edge;
    cudaGetSymbolAddress((void**)&z, g_z);
    cudaGetSymbolAddress((void**)&y, g_y);
    cudaGetSymbolAddress((void**)&h, g_h);
    cudaGetSymbolAddress((void**)&ds, g_deg_src);
    cudaGetSymbolAddress((void**)&dd, g_deg_dst);
    cudaGetSymbolAddress((void**)&cnt, g_cnt);
    cudaGetSymbolAddress((void**)&off, g_off);
    cudaGetSymbolAddress((void**)&cur, g_cursor);
    cudaGetSymbolAddress((void**)&edge, g_edge);
    cudaGetSymbolAddress((void**)&bsum, g_bsum);
    cudaGetSymbolAddress((void**)&boff, g_boff);

    const int SMEM_G = (2 * A_BUF + 2 * B_BUF) * 4;   // 54272 bytes
    cudaFuncSetAttribute(gemm_kernel<HF>,
                         cudaFuncAttributeMaxDynamicSharedMemorySize, SMEM_G);
    cudaFuncSetAttribute(gemm_kernel<OUTF>,
                         cudaFuncAttributeMaxDynamicSharedMemorySize, SMEM_G);

    // 1 init (+detect)
    init_kernel<<<512, 256>>>((const unsigned int*)srcI, NREL * E,
                              ds, dd, NREL * M, cnt, cur, M);
    // 2 degrees + counts
    degree_kernel<<<(NREL * E + 255) / 256, 256>>>(srcI, dstI, ds, dd, cnt, E, M);
    // 3 scanA
    scanA_kernel<<<NB, SCAN_B>>>(cnt, bsum, M);
    // 4 layer-1 GEMM (ncu capture slot)
    {
        dim3 grid(tiles, NREL, 2);
        gemm_kernel<HF><<<grid, 256, SMEM_G>>>(x, W1, z, M, Mp);
    }
    // 5-6 finish scan
    scanB_kernel<<<1, 32>>>(bsum, boff, off, NB, M);
    scanC_kernel<<<NB, SCAN_B>>>(cnt, boff, off, M);
    // 7 fill CSR
    fill_kernel<<<(NREL * E + 255) / 256, 256>>>(srcI, dstI, ds, dd,
                                                 off, cur, edge, E, M);
    // 8 layer-1 gather (+bias+relu)
    gather1_kernel<<<(M + 7) / 8, 256>>>(z, off, edge, b1, h, M, Mp);
    // 9 layer-2 GEMM
    {
        dim3 grid(tiles, NREL, 1);
        gemm_kernel<OUTF><<<grid, 256, SMEM_G>>>(h, W2, y, M, Mp);
    }
    // 10 layer-2 gather (+bias)
    gather2_kernel<<<(M + 15) / 16, 256>>>(y, off, edge, b2, out, M, Mp);
}

// round 12
// speedup vs baseline: 1.1941x; 1.1941x over previous
#include <cuda_runtime.h>
#include <cuda_bf16.h>
#include <math.h>
#include <stdint.h>
#include <mma.h>

using namespace nvcuda;

// ---------------------------------------------------------------------------
// RGCN, GEMM-first + CSR gather. wmma tf32 GEMM with 128x128 CTA tile,
// warp tile 32x64 (2x4 frags), KC=32 single-buffered, 2 CTAs/SM.
//   z_r = x @ W1_r ; h[d] = relu(sum_e coef_e * z[rel_e][src_e] + b1sum)
//   y_r = h @ W2_r ; out[d] =   sum_e coef_e * y[rel_e][src_e] + b2sum
// ---------------------------------------------------------------------------

#define NREL 4
#define INF  128
#define HF   128
#define OUTF 64
#define MAXN 100000
#define MAXE 400000
#define MAXT ((MAXN + 127) / 128)
#define MAXP (MAXT * 128)
#define SCAN_B 1024

__device__ float g_z[(size_t)NREL * MAXP * HF];
__device__ float g_y[(size_t)NREL * MAXP * OUTF];
__device__ float g_h[(size_t)MAXN * HF];
__device__ float g_deg_src[NREL * MAXN];
__device__ float g_deg_dst[NREL * MAXN];
__device__ int   g_cnt[MAXN + 1];
__device__ int   g_off[MAXN + 1];
__device__ int   g_cursor[MAXN];
__device__ int   g_bsum[128];
__device__ int   g_boff[128];
__device__ int2  g_edge[NREL * MAXE];   // .x = src | rel<<20, .y = coef bits
__device__ int   g_idx64;

__device__ __forceinline__ int load_idx(const void* p, size_t i, int is64) {
    return is64 ? (int)((const long long*)p)[i] : ((const int*)p)[i];
}

// ---------------------------------------------------------------------------
__global__ void init_kernel(const unsigned int* __restrict__ words, int n_words,
                            float* __restrict__ ds, float* __restrict__ dd, int nrs,
                            int* __restrict__ cnt, int* __restrict__ cur, int n) {
    if (blockIdx.x == 0) {
        int limit = n_words < 4096 ? n_words : 4096;
        int bad = 0;
        for (int i = 1 + 2 * (int)threadIdx.x; i < limit; i += 2 * (int)blockDim.x)
            bad |= (words[i] != 0u);
        bad = __syncthreads_or(bad);
        if (threadIdx.x == 0) g_idx64 = bad ? 0 : 1;
    }
    int i = blockIdx.x * blockDim.x + threadIdx.x;
    int st = gridDim.x * blockDim.x;
    for (int k = i; k < nrs; k += st) { ds[k] = 0.0f; dd[k] = 0.0f; }
    for (int k = i; k < n; k += st)   { cnt[k] = 0; cur[k] = 0; }
}

__global__ void degree_kernel(const void* __restrict__ src, const void* __restrict__ dst,
                              float* __restrict__ ds, float* __restrict__ dd,
                              int* __restrict__ cnt, int E, int M) {
    int i = blockIdx.x * blockDim.x + threadIdx.x;
    if (i >= NREL * E) return;
    const int is64 = g_idx64;
    int r = i / E;
    int s = load_idx(src, i, is64);
    int d = load_idx(dst, i, is64);
    atomicAdd(&ds[r * M + s], 1.0f);
    atomicAdd(&dd[r * M + d], 1.0f);
    atomicAdd(&cnt[d], 1);
}

// ---------------------------------------------------------------------------
__device__ __forceinline__ int block_incl_scan(int v, int* wsum) {
    const int lane = threadIdx.x & 31, wid = threadIdx.x >> 5;
    int s = v;
#pragma unroll
    for (int o = 1; o < 32; o <<= 1) {
        int t = __shfl_up_sync(~0u, s, o);
        if (lane >= o) s += t;
    }
    if (lane == 31) wsum[wid] = s;
    __syncthreads();
    if (wid == 0) {
        int ws = (lane < (SCAN_B / 32)) ? wsum[lane] : 0;
#pragma unroll
        for (int o = 1; o < 32; o <<= 1) {
            int t = __shfl_up_sync(~0u, ws, o);
            if (lane >= o) ws += t;
        }
        wsum[lane] = ws;
    }
    __syncthreads();
    return s + (wid > 0 ? wsum[wid - 1] : 0);
}

__global__ void scanA_kernel(const int* __restrict__ cnt, int* __restrict__ bsum, int n) {
    __shared__ int wsum[32];
    int i = blockIdx.x * SCAN_B + threadIdx.x;
    int v = (i < n) ? cnt[i] : 0;
    int s = block_incl_scan(v, wsum);
    if (threadIdx.x == SCAN_B - 1) bsum[blockIdx.x] = s;
}

__global__ void scanB_kernel(const int* __restrict__ bsum, int* __restrict__ boff,
                             int* __restrict__ off, int nb, int n) {
    const int lane = threadIdx.x;
    int carry = 0;
    for (int base = 0; base < nb; base += 32) {
        int i = base + lane;
        int v = (i < nb) ? bsum[i] : 0;
        int s = v;
#pragma unroll
        for (int o = 1; o < 32; o <<= 1) {
            int t = __shfl_up_sync(~0u, s, o);
            if (lane >= o) s += t;
        }
        if (i < nb) boff[i] = carry + s - v;
        carry += __shfl_sync(~0u, s, 31);
    }
    if (lane == 0) off[n] = carry;
}

__global__ void scanC_kernel(const int* __restrict__ cnt, const int* __restrict__ boff,
                             int* __restrict__ off, int n) {
    __shared__ int wsum[32];
    int i = blockIdx.x * SCAN_B + threadIdx.x;
    int v = (i < n) ? cnt[i] : 0;
    int s = block_incl_scan(v, wsum);
    if (i < n) off[i] = boff[blockIdx.x] + s - v;
}

// ---------------------------------------------------------------------------
__global__ void fill_kernel(const void* __restrict__ src, const void* __restrict__ dst,
                            const float* __restrict__ ds, const float* __restrict__ dd,
                            const int* __restrict__ off, int* __restrict__ cur,
                            int2* __restrict__ edge, int E, int M) {
    int i = blockIdx.x * blockDim.x + threadIdx.x;
    if (i >= NREL * E) return;
    const int is64 = g_idx64;
    int r = i / E;
    int s = load_idx(src, i, is64);
    int d = load_idx(dst, i, is64);
    int pos = off[d] + atomicAdd(&cur[d], 1);
    float coef = rsqrtf(fmaxf(ds[r * M + s], 1.0f)) *
                 rsqrtf(fmaxf(dd[r * M + d], 1.0f));
    edge[pos] = make_int2(s | (r << 20), __float_as_int(coef));
}

// ---------------------------------------------------------------------------
// wmma tf32 GEMM. CTA tile 128(M) x NF(N); warp tile 32 x NF/2.
// KC=32 single-buffered static SMEM (35 KB @ NF=128) -> 2 CTAs/SM.
// C[r] padded to Mp rows.
// ---------------------------------------------------------------------------
template <int NF>
__global__ __launch_bounds__(256, 2)
void gemm_kernel(const float* __restrict__ A, const float* __restrict__ B,
                 float* __restrict__ C, int M, int Mp) {
    constexpr int NFRAG = NF / 32;          // frags per warp along N (4 or 2)
    constexpr int BITER = (32 * NF / 4) / 256;
    __shared__ float As[128][36];
    __shared__ float Bs[32][NF + 4];

    const int r    = blockIdx.y;
    const int row0 = blockIdx.x * 128;
    const int tid  = threadIdx.x;
    const int wid  = tid >> 5;
    const int wm   = wid >> 1;              // 0..3 (M)
    const int wn   = wid & 1;               // 0..1 (N)
    const float* Br = B + (size_t)r * 128 * NF;

    const int arr = tid >> 1;               // A stage row
    const int acb = (tid & 1) * 16;         // A stage col base

    wmma::fragment<wmma::accumulator, 16, 16, 8, float> acc[2][NFRAG];
#pragma unroll
    for (int m = 0; m < 2; m++)
#pragma unroll
        for (int n = 0; n < NFRAG; n++) wmma::fill_fragment(acc[m][n], 0.0f);

#pragma unroll
    for (int kc = 0; kc < 4; kc++) {
        const int k0 = kc * 32;
        // stage A chunk (128 x 32)
        {
            const int gr = row0 + arr;
            const float* Arow = A + (size_t)gr * 128 + k0 + acb;
#pragma unroll
            for (int j = 0; j < 4; j++) {
                float4 v = (gr < M) ? *(const float4*)(Arow + j * 4)
                                    : make_float4(0.f, 0.f, 0.f, 0.f);
                float* p = &As[arr][acb + j * 4];
                p[0] = wmma::__float_to_tf32(v.x);
                p[1] = wmma::__float_to_tf32(v.y);
                p[2] = wmma::__float_to_tf32(v.z);
                p[3] = wmma::__float_to_tf32(v.w);
            }
        }
        // stage B chunk (32 x NF)
#pragma unroll
        for (int i = 0; i < BITER; i++) {
            int idx = tid + i * 256;
            int rr = idx / (NF / 4);
            int cc = (idx % (NF / 4)) * 4;
            float4 v = *(const float4*)(Br + (size_t)(k0 + rr) * NF + cc);
            float* p = &Bs[rr][cc];
            p[0] = wmma::__float_to_tf32(v.x);
            p[1] = wmma::__float_to_tf32(v.y);
            p[2] = wmma::__float_to_tf32(v.z);
            p[3] = wmma::__float_to_tf32(v.w);
        }
        __syncthreads();
#pragma unroll
        for (int kf = 0; kf < 4; kf++) {
            wmma::fragment<wmma::matrix_a, 16, 16, 8, wmma::precision::tf32,
                           wmma::row_major> a0, a1;
            wmma::load_matrix_sync(a0, &As[wm * 32 + 0][kf * 8], 36);
            wmma::load_matrix_sync(a1, &As[wm * 32 + 16][kf * 8], 36);
#pragma unroll
            for (int n = 0; n < NFRAG; n++) {
                wmma::fragment<wmma::matrix_b, 16, 16, 8, wmma::precision::tf32,
                               wmma::row_major> b;
                wmma::load_matrix_sync(b, &Bs[kf * 8][wn * (NF / 2) + n * 16],
                                       NF + 4);
                wmma::mma_sync(acc[0][n], a0, b, acc[0][n]);
                wmma::mma_sync(acc[1][n], a1, b, acc[1][n]);
            }
        }
        __syncthreads();
    }

    // epilogue: padded C rows -> no guard
#pragma unroll
    for (int m = 0; m < 2; m++) {
        float* Crow = C + ((size_t)r * Mp + row0 + wm * 32 + m * 16) * NF
                        + wn * (NF / 2);
#pragma unroll
        for (int n = 0; n < NFRAG; n++)
            wmma::store_matrix_sync(Crow + n * 16, acc[m][n], NF,
                                    wmma::mem_row_major);
    }
}

// ---------------------------------------------------------------------------
// gather1: warp per dst, 128 feats; h = relu(agg + b1sum)
__global__ __launch_bounds__(256)
void gather1_kernel(const float* __restrict__ Z, const int* __restrict__ off,
                    const int2* __restrict__ edge,
                    const float* __restrict__ b1, float* __restrict__ h,
                    int M, int Mp) {
    const int d = blockIdx.x * 8 + (threadIdx.x >> 5);
    const int lane = threadIdx.x & 31;
    if (d >= M) return;
    const int e0 = off[d], e1 = off[d + 1];
    float4 acc = make_float4(0.f, 0.f, 0.f, 0.f);
#pragma unroll 8
    for (int e = e0; e < e1; e++) {
        const int2 ed = __ldg(&edge[e]);
        const int s = ed.x & 0xFFFFF, r = ed.x >> 20;
        const float c = __int_as_float(ed.y);
        const float4 v = *(const float4*)(Z + ((size_t)r * Mp + s) * 128 + lane * 4);
        acc.x += c * v.x; acc.y += c * v.y; acc.z += c * v.z; acc.w += c * v.w;
    }
    const int f = lane * 4;
    float4 o;
    o.x = fmaxf(acc.x + b1[f+0] + b1[128+f+0] + b1[256+f+0] + b1[384+f+0], 0.f);
    o.y = fmaxf(acc.y + b1[f+1] + b1[128+f+1] + b1[256+f+1] + b1[384+f+1], 0.f);
    o.z = fmaxf(acc.z + b1[f+2] + b1[128+f+2] + b1[256+f+2] + b1[384+f+2], 0.f);
    o.w = fmaxf(acc.w + b1[f+3] + b1[128+f+3] + b1[256+f+3] + b1[384+f+3], 0.f);
    *(float4*)(h + (size_t)d * 128 + f) = o;
}

// gather2: half-warp per dst, 64 feats; out = agg + b2sum
__global__ __launch_bounds__(256)
void gather2_kernel(const float* __restrict__ Y, const int* __restrict__ off,
                    const int2* __restrict__ edge,
                    const float* __restrict__ b2, float* __restrict__ out,
                    int M, int Mp) {
    const int warp = blockIdx.x * 8 + (threadIdx.x >> 5);
    const int lane = threadIdx.x & 31;
    const int d = warp * 2 + (lane >> 4);
    const int fl = lane & 15;
    if (d >= M) return;
    const int e0 = off[d], e1 = off[d + 1];
    float4 acc = make_float4(0.f, 0.f, 0.f, 0.f);
#pragma unroll 8
    for (int e = e0; e < e1; e++) {
        const int2 ed = __ldg(&edge[e]);
        const int s = ed.x & 0xFFFFF, r = ed.x >> 20;
        const float c = __int_as_float(ed.y);
        const float4 v = *(const float4*)(Y + ((size_t)r * Mp + s) * 64 + fl * 4);
        acc.x += c * v.x; acc.y += c * v.y; acc.z += c * v.z; acc.w += c * v.w;
    }
    const int f = fl * 4;
    float4 o;
    o.x = acc.x + b2[f+0] + b2[64+f+0] + b2[128+f+0] + b2[192+f+0];
    o.y = acc.y + b2[f+1] + b2[64+f+1] + b2[128+f+1] + b2[192+f+1];
    o.z = acc.z + b2[f+2] + b2[64+f+2] + b2[128+f+2] + b2[192+f+2];
    o.w = acc.w + b2[f+3] + b2[64+f+3] + b2[128+f+3] + b2[192+f+3];
    *(float4*)(out + (size_t)d * 64 + f) = o;
}

// ---------------------------------------------------------------------------
extern "C" void kernel_launch(void* const* d_in, const int* in_sizes, int n_in,
                              void* d_out, int out_size) {
    const float* x    = (const float*)d_in[0];
    const void*  srcI = d_in[1];
    const void*  dstI = d_in[2];
    const float* W1   = (const float*)d_in[3];
    const float* b1   = (const float*)d_in[4];
    const float* W2   = (const float*)d_in[5];
    const float* b2   = (const float*)d_in[6];
    float*       out  = (float*)d_out;

    const int M = in_sizes[0] / INF;
    const int E = in_sizes[1] / NREL;
    const int tiles = (M + 127) / 128;
    const int Mp = tiles * 128;
    const int NB = (M + SCAN_B - 1) / SCAN_B;

    float *z, *y, *h, *ds, *dd;
    int *cnt, *off, *cur, *bsum, *boff;
    int2 *edge;
    cudaGetSymbolAddress((void**)&z, g_z);
    cudaGetSymbolAddress((void**)&y, g_y);
    cudaGetSymbolAddress((void**)&h, g_h);
    cudaGetSymbolAddress((void**)&ds, g_deg_src);
    cudaGetSymbolAddress((void**)&dd, g_deg_dst);
    cudaGetSymbolAddress((void**)&cnt, g_cnt);
    cudaGetSymbolAddress((void**)&off, g_off);
    cudaGetSymbolAddress((void**)&cur, g_cursor);
    cudaGetSymbolAddress((void**)&edge, g_edge);
    cudaGetSymbolAddress((void**)&bsum, g_bsum);
    cudaGetSymbolAddress((void**)&boff, g_boff);

    // 1 init (+detect)
    init_kernel<<<512, 256>>>((const unsigned int*)srcI, NREL * E,
                              ds, dd, NREL * M, cnt, cur, M);
    // 2 degrees + counts
    degree_kernel<<<(NREL * E + 255) / 256, 256>>>(srcI, dstI, ds, dd, cnt, E, M);
    // 3 scanA
    scanA_kernel<<<NB, SCAN_B>>>(cnt, bsum, M);
    // 4 layer-1 GEMM (ncu capture slot)
    {
        dim3 grid(tiles, NREL);
        gemm_kernel<HF><<<grid, 256>>>(x, W1, z, M, Mp);
    }
    // 5-6 finish scan
    scanB_kernel<<<1, 32>>>(bsum, boff, off, NB, M);
    scanC_kernel<<<NB, SCAN_B>>>(cnt, boff, off, M);
    // 7 fill CSR
    fill_kernel<<<(NREL * E + 255) / 256, 256>>>(srcI, dstI, ds, dd,
                                                 off, cur, edge, E, M);
    // 8 layer-1 gather (+bias+relu)
    gather1_kernel<<<(M + 7) / 8, 256>>>(z, off, edge, b1, h, M, Mp);
    // 9 layer-2 GEMM
    {
        dim3 grid(tiles, NREL);
        gemm_kernel<OUTF><<<grid, 256>>>(h, W2, y, M, Mp);
    }
    // 10 layer-2 gather (+bias)
    gather2_kernel<<<(M + 15) / 16, 256>>>(y, off, edge, b2, out, M, Mp);
}

// round 14
// speedup vs baseline: 1.2016x; 1.0063x over previous
#include <cuda_runtime.h>
#include <cuda_bf16.h>
#include <math.h>
#include <stdint.h>
#include <mma.h>

using namespace nvcuda;

// ---------------------------------------------------------------------------
// RGCN, GEMM-first + CSR gather. wmma tf32 GEMM, 128x128 CTA tile, warp tile
// 32x(NF/2), KC=32 double-buffered via cp.async. Fragments are rounded to
// tf32 (RN) in-register after load (raw-bit HMMA truncation fails 1e-3).
//   z_r = x @ W1_r ; h[d] = relu(sum_e coef_e * z[rel_e][src_e] + b1sum)
//   y_r = h @ W2_r ; out[d] =   sum_e coef_e * y[rel_e][src_e] + b2sum
// ---------------------------------------------------------------------------

#define NREL 4
#define INF  128
#define HF   128
#define OUTF 64
#define MAXN 100000
#define MAXE 400000
#define MAXT ((MAXN + 127) / 128)
#define MAXP (MAXT * 128)
#define SCAN_B 1024

__device__ float g_z[(size_t)NREL * MAXP * HF];
__device__ float g_y[(size_t)NREL * MAXP * OUTF];
__device__ float g_h[(size_t)MAXN * HF];
__device__ float g_deg_src[NREL * MAXN];
__device__ float g_deg_dst[NREL * MAXN];
__device__ int   g_cnt[MAXN + 1];
__device__ int   g_off[MAXN + 1];
__device__ int   g_cursor[MAXN];
__device__ int   g_bsum[128];
__device__ int   g_boff[128];
__device__ int2  g_edge[NREL * MAXE];   // .x = src | rel<<20, .y = coef bits
__device__ int   g_idx64;

__device__ __forceinline__ int load_idx(const void* p, size_t i, int is64) {
    return is64 ? (int)((const long long*)p)[i] : ((const int*)p)[i];
}

__device__ __forceinline__ void cp16(void* smem, const void* gmem, int src_sz) {
    uint32_t d = (uint32_t)__cvta_generic_to_shared(smem);
    asm volatile("cp.async.cg.shared.global [%0], [%1], 16, %2;"
                 :: "r"(d), "l"(gmem), "r"(src_sz) : "memory");
}
__device__ __forceinline__ void cp16(void* smem, const void* gmem) {
    uint32_t d = (uint32_t)__cvta_generic_to_shared(smem);
    asm volatile("cp.async.cg.shared.global [%0], [%1], 16;"
                 :: "r"(d), "l"(gmem) : "memory");
}
#define CP_COMMIT() asm volatile("cp.async.commit_group;" ::: "memory")
#define CP_WAIT(n)  asm volatile("cp.async.wait_group %0;" :: "n"(n) : "memory")

// ---------------------------------------------------------------------------
__global__ void init_kernel(const unsigned int* __restrict__ words, int n_words,
                            float* __restrict__ ds, float* __restrict__ dd, int nrs,
                            int* __restrict__ cnt, int* __restrict__ cur, int n) {
    if (blockIdx.x == 0) {
        int limit = n_words < 4096 ? n_words : 4096;
        int bad = 0;
        for (int i = 1 + 2 * (int)threadIdx.x; i < limit; i += 2 * (int)blockDim.x)
            bad |= (words[i] != 0u);
        bad = __syncthreads_or(bad);
        if (threadIdx.x == 0) g_idx64 = bad ? 0 : 1;
    }
    int i = blockIdx.x * blockDim.x + threadIdx.x;
    int st = gridDim.x * blockDim.x;
    for (int k = i; k < nrs; k += st) { ds[k] = 0.0f; dd[k] = 0.0f; }
    for (int k = i; k < n; k += st)   { cnt[k] = 0; cur[k] = 0; }
}

__global__ void degree_kernel(const void* __restrict__ src, const void* __restrict__ dst,
                              float* __restrict__ ds, float* __restrict__ dd,
                              int* __restrict__ cnt, int E, int M) {
    int i = blockIdx.x * blockDim.x + threadIdx.x;
    if (i >= NREL * E) return;
    const int is64 = g_idx64;
    int r = i / E;
    int s = load_idx(src, i, is64);
    int d = load_idx(dst, i, is64);
    atomicAdd(&ds[r * M + s], 1.0f);
    atomicAdd(&dd[r * M + d], 1.0f);
    atomicAdd(&cnt[d], 1);
}

// ---------------------------------------------------------------------------
__device__ __forceinline__ int block_incl_scan(int v, int* wsum) {
    const int lane = threadIdx.x & 31, wid = threadIdx.x >> 5;
    int s = v;
#pragma unroll
    for (int o = 1; o < 32; o <<= 1) {
        int t = __shfl_up_sync(~0u, s, o);
        if (lane >= o) s += t;
    }
    if (lane == 31) wsum[wid] = s;
    __syncthreads();
    if (wid == 0) {
        int ws = (lane < (SCAN_B / 32)) ? wsum[lane] : 0;
#pragma unroll
        for (int o = 1; o < 32; o <<= 1) {
            int t = __shfl_up_sync(~0u, ws, o);
            if (lane >= o) ws += t;
        }
        wsum[lane] = ws;
    }
    __syncthreads();
    return s + (wid > 0 ? wsum[wid - 1] : 0);
}

__global__ void scanA_kernel(const int* __restrict__ cnt, int* __restrict__ bsum, int n) {
    __shared__ int wsum[32];
    int i = blockIdx.x * SCAN_B + threadIdx.x;
    int v = (i < n) ? cnt[i] : 0;
    int s = block_incl_scan(v, wsum);
    if (threadIdx.x == SCAN_B - 1) bsum[blockIdx.x] = s;
}

__global__ void scanB_kernel(const int* __restrict__ bsum, int* __restrict__ boff,
                             int* __restrict__ off, int nb, int n) {
    const int lane = threadIdx.x;
    int carry = 0;
    for (int base = 0; base < nb; base += 32) {
        int i = base + lane;
        int v = (i < nb) ? bsum[i] : 0;
        int s = v;
#pragma unroll
        for (int o = 1; o < 32; o <<= 1) {
            int t = __shfl_up_sync(~0u, s, o);
            if (lane >= o) s += t;
        }
        if (i < nb) boff[i] = carry + s - v;
        carry += __shfl_sync(~0u, s, 31);
    }
    if (lane == 0) off[n] = carry;
}

__global__ void scanC_kernel(const int* __restrict__ cnt, const int* __restrict__ boff,
                             int* __restrict__ off, int n) {
    __shared__ int wsum[32];
    int i = blockIdx.x * SCAN_B + threadIdx.x;
    int v = (i < n) ? cnt[i] : 0;
    int s = block_incl_scan(v, wsum);
    if (i < n) off[i] = boff[blockIdx.x] + s - v;
}

// ---------------------------------------------------------------------------
__global__ void fill_kernel(const void* __restrict__ src, const void* __restrict__ dst,
                            const float* __restrict__ ds, const float* __restrict__ dd,
                            const int* __restrict__ off, int* __restrict__ cur,
                            int2* __restrict__ edge, int E, int M) {
    int i = blockIdx.x * blockDim.x + threadIdx.x;
    if (i >= NREL * E) return;
    const int is64 = g_idx64;
    int r = i / E;
    int s = load_idx(src, i, is64);
    int d = load_idx(dst, i, is64);
    int pos = off[d] + atomicAdd(&cur[d], 1);
    float coef = rsqrtf(fmaxf(ds[r * M + s], 1.0f)) *
                 rsqrtf(fmaxf(dd[r * M + d], 1.0f));
    edge[pos] = make_int2(s | (r << 20), __float_as_int(coef));
}

// ---------------------------------------------------------------------------
// wmma tf32 GEMM. CTA tile 128(M) x NF(N); warp tile 32 x NF/2.
// KC=32 double-buffered cp.async. Fragments rounded to tf32 (RN) in-register.
// ---------------------------------------------------------------------------
template <typename Frag>
__device__ __forceinline__ void round_tf32(Frag& f) {
#pragma unroll
    for (int i = 0; i < f.num_elements; i++)
        f.x[i] = wmma::__float_to_tf32(f.x[i]);
}

template <int NF>
__global__ __launch_bounds__(256, 2)
void gemm_kernel(const float* __restrict__ A, const float* __restrict__ B,
                 float* __restrict__ C, int M, int Mp) {
    constexpr int NFRAG = NF / 32;
    constexpr int AST = 36, BST = NF + 4;
    constexpr int ABUF = 128 * AST, BBUF = 32 * BST;
    constexpr int BCH = (32 * NF / 4) / 256;
    extern __shared__ float sm[];
    float* As = sm;                  // [2][128][AST]
    float* Bs = sm + 2 * ABUF;       // [2][32][BST]

    const int r    = blockIdx.y;
    const int row0 = blockIdx.x * 128;
    const int tid  = threadIdx.x;
    const int wid  = tid >> 5;
    const int wm   = wid >> 1;
    const int wn   = wid & 1;
    const float* Br = B + (size_t)r * 128 * NF;

    const int arr = tid >> 1;
    const int acb = (tid & 1) * 16;
    const int gr  = row0 + arr;
    const int asz = (gr < M) ? 16 : 0;
    const float* Arow = A + (size_t)gr * 128 + acb;

    auto stage = [&](int kc, int buf) {
        float* Ab = As + buf * ABUF + arr * AST + acb;
        const float* Ag = Arow + kc * 32;
#pragma unroll
        for (int j = 0; j < 4; j++)
            cp16(Ab + j * 4, Ag + j * 4, asz);
#pragma unroll
        for (int i = 0; i < BCH; i++) {
            int idx = tid + i * 256;
            int rr = idx / (NF / 4);
            int cc = (idx % (NF / 4)) * 4;
            cp16(Bs + buf * BBUF + rr * BST + cc,
                 Br + (size_t)(kc * 32 + rr) * NF + cc);
        }
        CP_COMMIT();
    };

    wmma::fragment<wmma::accumulator, 16, 16, 8, float> acc[2][NFRAG];
#pragma unroll
    for (int m = 0; m < 2; m++)
#pragma unroll
        for (int n = 0; n < NFRAG; n++) wmma::fill_fragment(acc[m][n], 0.0f);

    stage(0, 0);
#pragma unroll
    for (int kc = 0; kc < 4; kc++) {
        const int cur = kc & 1;
        if (kc < 3) {
            stage(kc + 1, cur ^ 1);
            CP_WAIT(1);
        } else {
            CP_WAIT(0);
        }
        __syncthreads();
        const float* Ab = As + cur * ABUF + (wm * 32) * AST;
        const float* Bb = Bs + cur * BBUF + wn * (NF / 2);
#pragma unroll
        for (int kf = 0; kf < 4; kf++) {
            wmma::fragment<wmma::matrix_a, 16, 16, 8, wmma::precision::tf32,
                           wmma::row_major> a0, a1;
            wmma::load_matrix_sync(a0, Ab + kf * 8, AST);
            wmma::load_matrix_sync(a1, Ab + 16 * AST + kf * 8, AST);
            round_tf32(a0);
            round_tf32(a1);
#pragma unroll
            for (int n = 0; n < NFRAG; n++) {
                wmma::fragment<wmma::matrix_b, 16, 16, 8, wmma::precision::tf32,
                               wmma::row_major> b;
                wmma::load_matrix_sync(b, Bb + (kf * 8) * BST + n * 16, BST);
                round_tf32(b);
                wmma::mma_sync(acc[0][n], a0, b, acc[0][n]);
                wmma::mma_sync(acc[1][n], a1, b, acc[1][n]);
            }
        }
        __syncthreads();
    }

#pragma unroll
    for (int m = 0; m < 2; m++) {
        float* Crow = C + ((size_t)r * Mp + row0 + wm * 32 + m * 16) * NF
                        + wn * (NF / 2);
#pragma unroll
        for (int n = 0; n < NFRAG; n++)
            wmma::store_matrix_sync(Crow + n * 16, acc[m][n], NF,
                                    wmma::mem_row_major);
    }
}

// ---------------------------------------------------------------------------
// gather1: warp per dst, 128 feats; h = relu(agg + b1sum)
__global__ __launch_bounds__(256)
void gather1_kernel(const float* __restrict__ Z, const int* __restrict__ off,
                    const int2* __restrict__ edge,
                    const float* __restrict__ b1, float* __restrict__ h,
                    int M, int Mp) {
    const int d = blockIdx.x * 8 + (threadIdx.x >> 5);
    const int lane = threadIdx.x & 31;
    if (d >= M) return;
    const int e0 = off[d], e1 = off[d + 1];
    float4 acc = make_float4(0.f, 0.f, 0.f, 0.f);
#pragma unroll 8
    for (int e = e0; e < e1; e++) {
        const int2 ed = __ldg(&edge[e]);
        const int s = ed.x & 0xFFFFF, r = ed.x >> 20;
        const float c = __int_as_float(ed.y);
        const float4 v = *(const float4*)(Z + ((size_t)r * Mp + s) * 128 + lane * 4);
        acc.x += c * v.x; acc.y += c * v.y; acc.z += c * v.z; acc.w += c * v.w;
    }
    const int f = lane * 4;
    float4 o;
    o.x = fmaxf(acc.x + b1[f+0] + b1[128+f+0] + b1[256+f+0] + b1[384+f+0], 0.f);
    o.y = fmaxf(acc.y + b1[f+1] + b1[128+f+1] + b1[256+f+1] + b1[384+f+1], 0.f);
    o.z = fmaxf(acc.z + b1[f+2] + b1[128+f+2] + b1[256+f+2] + b1[384+f+2], 0.f);
    o.w = fmaxf(acc.w + b1[f+3] + b1[128+f+3] + b1[256+f+3] + b1[384+f+3], 0.f);
    *(float4*)(h + (size_t)d * 128 + f) = o;
}

// gather2: half-warp per dst, 64 feats; out = agg + b2sum
__global__ __launch_bounds__(256)
void gather2_kernel(const float* __restrict__ Y, const int* __restrict__ off,
                    const int2* __restrict__ edge,
                    const float* __restrict__ b2, float* __restrict__ out,
                    int M, int Mp) {
    const int warp = blockIdx.x * 8 + (threadIdx.x >> 5);
    const int lane = threadIdx.x & 31;
    const int d = warp * 2 + (lane >> 4);
    const int fl = lane & 15;
    if (d >= M) return;
    const int e0 = off[d], e1 = off[d + 1];
    float4 acc = make_float4(0.f, 0.f, 0.f, 0.f);
#pragma unroll 8
    for (int e = e0; e < e1; e++) {
        const int2 ed = __ldg(&edge[e]);
        const int s = ed.x & 0xFFFFF, r = ed.x >> 20;
        const float c = __int_as_float(ed.y);
        const float4 v = *(const float4*)(Y + ((size_t)r * Mp + s) * 64 + fl * 4);
        acc.x += c * v.x; acc.y += c * v.y; acc.z += c * v.z; acc.w += c * v.w;
    }
    const int f = fl * 4;
    float4 o;
    o.x = acc.x + b2[f+0] + b2[64+f+0] + b2[128+f+0] + b2[192+f+0];
    o.y = acc.y + b2[f+1] + b2[64+f+1] + b2[128+f+1] + b2[192+f+1];
    o.z = acc.z + b2[f+2] + b2[64+f+2] + b2[128+f+2] + b2[192+f+2];
    o.w = acc.w + b2[f+3] + b2[64+f+3] + b2[128+f+3] + b2[192+f+3];
    *(float4*)(out + (size_t)d * 64 + f) = o;
}

// ---------------------------------------------------------------------------
extern "C" void kernel_launch(void* const* d_in, const int* in_sizes, int n_in,
                              void* d_out, int out_size) {
    const float* x    = (const float*)d_in[0];
    const void*  srcI = d_in[1];
    const void*  dstI = d_in[2];
    const float* W1   = (const float*)d_in[3];
    const float* b1   = (const float*)d_in[4];
    const float* W2   = (const float*)d_in[5];
    const float* b2   = (const float*)d_in[6];
    float*       out  = (float*)d_out;

    const int M = in_sizes[0] / INF;
    const int E = in_sizes[1] / NREL;
    const int tiles = (M + 127) / 128;
    const int Mp = tiles * 128;
    const int NB = (M + SCAN_B - 1) / SCAN_B;

    float *z, *y, *h, *ds, *dd;
    int *cnt, *off, *cur, *bsum, *boff;
    int2 *edge;
    cudaGetSymbolAddress((void**)&z, g_z);
    cudaGetSymbolAddress((void**)&y, g_y);
    cudaGetSymbolAddress((void**)&h, g_h);
    cudaGetSymbolAddress((void**)&ds, g_deg_src);
    cudaGetSymbolAddress((void**)&dd, g_deg_dst);
    cudaGetSymbolAddress((void**)&cnt, g_cnt);
    cudaGetSymbolAddress((void**)&off, g_off);
    cudaGetSymbolAddress((void**)&cur, g_cursor);
    cudaGetSymbolAddress((void**)&edge, g_edge);
    cudaGetSymbolAddress((void**)&bsum, g_bsum);
    cudaGetSymbolAddress((void**)&boff, g_boff);

    const int SMEM1 = (2 * 128 * 36 + 2 * 32 * (HF + 4)) * 4;    // 70656
    const int SMEM2 = (2 * 128 * 36 + 2 * 32 * (OUTF + 4)) * 4;  // 54272
    cudaFuncSetAttribute(gemm_kernel<HF>,
                         cudaFuncAttributeMaxDynamicSharedMemorySize, SMEM1);
    cudaFuncSetAttribute(gemm_kernel<OUTF>,
                         cudaFuncAttributeMaxDynamicSharedMemorySize, SMEM2);

    // 1 init (+detect)
    init_kernel<<<512, 256>>>((const unsigned int*)srcI, NREL * E,
                              ds, dd, NREL * M, cnt, cur, M);
    // 2 degrees + counts
    degree_kernel<<<(NREL * E + 255) / 256, 256>>>(srcI, dstI, ds, dd, cnt, E, M);
    // 3 scanA
    scanA_kernel<<<NB, SCAN_B>>>(cnt, bsum, M);
    // 4 layer-1 GEMM (ncu capture slot)
    {
        dim3 grid(tiles, NREL);
        gemm_kernel<HF><<<grid, 256, SMEM1>>>(x, W1, z, M, Mp);
    }
    // 5-6 finish scan
    scanB_kernel<<<1, 32>>>(bsum, boff, off, NB, M);
    scanC_kernel<<<NB, SCAN_B>>>(cnt, boff, off, M);
    // 7 fill CSR
    fill_kernel<<<(NREL * E + 255) / 256, 256>>>(srcI, dstI, ds, dd,
                                                 off, cur, edge, E, M);
    // 8 layer-1 gather (+bias+relu)
    gather1_kernel<<<(M + 7) / 8, 256>>>(z, off, edge, b1, h, M, Mp);
    // 9 layer-2 GEMM
    {
        dim3 grid(tiles, NREL);
        gemm_kernel<OUTF><<<grid, 256, SMEM2>>>(h, W2, y, M, Mp);
    }
    // 10 layer-2 gather (+bias)
    gather2_kernel<<<(M + 15) / 16, 256>>>(y, off, edge, b2, out, M, Mp);
}